// round 3
// baseline (speedup 1.0000x reference)
#include <cuda_runtime.h>
#include <math.h>

// Problem dims (fixed by the dataset)
#define B_SZ 32768
#define H_SZ 896          // hidden
#define S_SZ 448          // H/2
#define Q_SZ 256
#define H3   (3 * H_SZ)   // 2688
#define S3   (3 * S_SZ)   // 1344

// ---------------------------------------------------------------------------
// Scratch (device globals: allocation-free per harness rules)
// ---------------------------------------------------------------------------
__device__ float g_Rh[(size_t)B_SZ * H3];   // R_hidden [B, 3H]  (352 MB)
__device__ float g_hc[(size_t)B_SZ * S_SZ]; // relu(hidden_c @ O1 + b1)
__device__ float g_hf[(size_t)B_SZ * S_SZ]; // relu(hidden_f @ O3 + b3)

// ---------------------------------------------------------------------------
// SGEMM: C[M,N] = A[M,K] @ B[K,N] (+bias)(+relu). Row-major everything.
// BM=128, BN=128, BK=8, 256 threads, 8x8 microtile per thread.
// M must be a multiple of 128 (true: 32768). K must be a multiple of 8
// (896, 448 ok). N handled with guards (2688, 448, 256).
// ---------------------------------------------------------------------------
template <int EPI>   // 0 = none, 1 = bias+relu, 2 = bias
__global__ void __launch_bounds__(256, 2)
sgemm128(const float* __restrict__ A, int lda,
         const float* __restrict__ Bm, int ldb,
         const float* __restrict__ bias,
         float* __restrict__ C, int ldc,
         int N, int K)
{
    __shared__ float As[8][128];
    __shared__ float Bs[8][128];

    const int tid = threadIdx.x;
    const int tx  = tid & 15;   // 0..15 (col group)
    const int ty  = tid >> 4;   // 0..15 (row group)

    const int rowC0 = blockIdx.y * 128 + ty * 8;
    const int colC0 = blockIdx.x * 128 + tx * 8;

    // global->smem load mapping
    const int aRow = tid >> 1;          // 0..127
    const int aCol = (tid & 1) * 4;     // 0 or 4
    const int bRow = tid >> 5;          // 0..7
    const int bCol = (tid & 31) * 4;    // 0..124

    const float* Ag    = A + (size_t)(blockIdx.y * 128 + aRow) * lda + aCol;
    const int    bColG = blockIdx.x * 128 + bCol;
    const float* Bg    = Bm + (size_t)bRow * ldb + bColG;
    const bool   bOk   = (bColG < N);   // N % 4 == 0, so float4 all-in/all-out

    float acc[8][8];
    #pragma unroll
    for (int i = 0; i < 8; ++i)
        #pragma unroll
        for (int j = 0; j < 8; ++j) acc[i][j] = 0.0f;

    for (int k0 = 0; k0 < K; k0 += 8) {
        // --- stage A tile (transposed into smem) ---
        float4 av = *reinterpret_cast<const float4*>(Ag + k0);
        As[aCol + 0][aRow] = av.x;
        As[aCol + 1][aRow] = av.y;
        As[aCol + 2][aRow] = av.z;
        As[aCol + 3][aRow] = av.w;
        // --- stage B tile ---
        float4 bv = make_float4(0.f, 0.f, 0.f, 0.f);
        if (bOk) bv = *reinterpret_cast<const float4*>(Bg + (size_t)k0 * ldb);
        *reinterpret_cast<float4*>(&Bs[bRow][bCol]) = bv;
        __syncthreads();

        #pragma unroll
        for (int k = 0; k < 8; ++k) {
            float ra[8], rb[8];
            *reinterpret_cast<float4*>(&ra[0]) = *reinterpret_cast<const float4*>(&As[k][ty * 8]);
            *reinterpret_cast<float4*>(&ra[4]) = *reinterpret_cast<const float4*>(&As[k][ty * 8 + 4]);
            *reinterpret_cast<float4*>(&rb[0]) = *reinterpret_cast<const float4*>(&Bs[k][tx * 8]);
            *reinterpret_cast<float4*>(&rb[4]) = *reinterpret_cast<const float4*>(&Bs[k][tx * 8 + 4]);
            #pragma unroll
            for (int i = 0; i < 8; ++i)
                #pragma unroll
                for (int j = 0; j < 8; ++j)
                    acc[i][j] = fmaf(ra[i], rb[j], acc[i][j]);
        }
        __syncthreads();
    }

    // --- epilogue ---
    #pragma unroll
    for (int i = 0; i < 8; ++i) {
        const int row = rowC0 + i;
        #pragma unroll
        for (int j = 0; j < 8; j += 4) {
            const int col = colC0 + j;
            if (col < N) {
                float4 v = *reinterpret_cast<float4*>(&acc[i][j]);
                if (EPI >= 1) {
                    const float4 bb = *reinterpret_cast<const float4*>(bias + col);
                    v.x += bb.x; v.y += bb.y; v.z += bb.z; v.w += bb.w;
                    if (EPI == 1) {
                        v.x = fmaxf(v.x, 0.f); v.y = fmaxf(v.y, 0.f);
                        v.z = fmaxf(v.z, 0.f); v.w = fmaxf(v.w, 0.f);
                    }
                }
                *reinterpret_cast<float4*>(C + (size_t)row * ldc + col) = v;
            }
        }
    }
}

// ---------------------------------------------------------------------------
// GRU gate elementwise. Folds the rank-2 (coarse) / rank-3 (fine) input
// projections in directly. One thread per (b, h).
// ---------------------------------------------------------------------------
__global__ void gru_elem(const float* __restrict__ Rh,       // [B, 3H]
                         const float* __restrict__ prev_h,   // [B, H]
                         const float* __restrict__ prev_y,   // [B, 2]
                         const float* __restrict__ ccoarse,  // [B, 1]
                         const float* __restrict__ Icw,      // [2, 3S]
                         const float* __restrict__ Ifw,      // [3, 3S]
                         const float* __restrict__ bu,
                         const float* __restrict__ br,
                         const float* __restrict__ be,
                         float* __restrict__ hidden)         // [B, H]
{
    const int idx = blockIdx.x * blockDim.x + threadIdx.x;
    if (idx >= B_SZ * H_SZ) return;
    const int b = idx / H_SZ;
    const int h = idx - b * H_SZ;

    const float py0 = prev_y[2 * b];
    const float py1 = prev_y[2 * b + 1];

    float Iu, Ir, Ie;
    if (h < S_SZ) {
        // coarse half: prev_y @ I_coarse_W
        Iu = py0 * Icw[h]            + py1 * Icw[S3 + h];
        Ir = py0 * Icw[S_SZ + h]     + py1 * Icw[S3 + S_SZ + h];
        Ie = py0 * Icw[2 * S_SZ + h] + py1 * Icw[S3 + 2 * S_SZ + h];
    } else {
        // fine half: [prev_y, current_coarse] @ I_fine_W
        const int hh = h - S_SZ;
        const float c = ccoarse[b];
        Iu = py0 * Ifw[hh]            + py1 * Ifw[S3 + hh]            + c * Ifw[2 * S3 + hh];
        Ir = py0 * Ifw[S_SZ + hh]     + py1 * Ifw[S3 + S_SZ + hh]     + c * Ifw[2 * S3 + S_SZ + hh];
        Ie = py0 * Ifw[2 * S_SZ + hh] + py1 * Ifw[S3 + 2 * S_SZ + hh] + c * Ifw[2 * S3 + 2 * S_SZ + hh];
    }

    const float* r0 = Rh + (size_t)b * H3;
    const float Ru = r0[h];
    const float Rr = r0[H_SZ + h];
    const float Re = r0[2 * H_SZ + h];

    const float u = 1.0f / (1.0f + expf(-(Ru + Iu + bu[h])));
    const float r = 1.0f / (1.0f + expf(-(Rr + Ir + br[h])));
    const float e = tanhf(r * Re + Ie + be[h]);

    const float ph = prev_h[idx];
    hidden[idx] = u * ph + (1.0f - u) * e;
}

// ---------------------------------------------------------------------------
// Launch
// ---------------------------------------------------------------------------
extern "C" void kernel_launch(void* const* d_in, const int* in_sizes, int n_in,
                              void* d_out, int out_size)
{
    const float* prev_y   = (const float*)d_in[0];
    const float* prev_h   = (const float*)d_in[1];
    const float* ccoarse  = (const float*)d_in[2];
    const float* R_W      = (const float*)d_in[3];
    const float* Icw      = (const float*)d_in[4];
    const float* Ifw      = (const float*)d_in[5];
    const float* O1_W     = (const float*)d_in[6];
    const float* O1_b     = (const float*)d_in[7];
    const float* O2_W     = (const float*)d_in[8];
    const float* O2_b     = (const float*)d_in[9];
    const float* O3_W     = (const float*)d_in[10];
    const float* O3_b     = (const float*)d_in[11];
    const float* O4_W     = (const float*)d_in[12];
    const float* O4_b     = (const float*)d_in[13];
    const float* bu       = (const float*)d_in[14];
    const float* br       = (const float*)d_in[15];
    const float* be       = (const float*)d_in[16];

    float* out = (float*)d_out;
    float* out_coarse = out;                              // [B, Q]
    float* out_fine   = out + (size_t)B_SZ * Q_SZ;        // [B, Q]
    float* hidden     = out + (size_t)2 * B_SZ * Q_SZ;    // [B, H]

    float *Rh, *hc, *hf;
    cudaGetSymbolAddress((void**)&Rh, g_Rh);
    cudaGetSymbolAddress((void**)&hc, g_hc);
    cudaGetSymbolAddress((void**)&hf, g_hf);

    const int MT = B_SZ / 128;   // 256 M-tiles

    // 1) R_hidden = prev_hidden @ R_W   [32768,896]@[896,2688]
    sgemm128<0><<<dim3(H3 / 128, MT), 256>>>(prev_h, H_SZ, R_W, H3, nullptr,
                                             Rh, H3, H3, H_SZ);

    // 2) GRU gates -> hidden (into d_out)
    gru_elem<<<(B_SZ * H_SZ + 255) / 256, 256>>>(Rh, prev_h, prev_y, ccoarse,
                                                 Icw, Ifw, bu, br, be, hidden);

    // 3) hc = relu(hidden[:, :448] @ O1_W + O1_b)
    sgemm128<1><<<dim3(4, MT), 256>>>(hidden, H_SZ, O1_W, S_SZ, O1_b,
                                      hc, S_SZ, S_SZ, S_SZ);
    // 4) hf = relu(hidden[:, 448:] @ O3_W + O3_b)
    sgemm128<1><<<dim3(4, MT), 256>>>(hidden + S_SZ, H_SZ, O3_W, S_SZ, O3_b,
                                      hf, S_SZ, S_SZ, S_SZ);
    // 5) out_coarse = hc @ O2_W + O2_b
    sgemm128<2><<<dim3(2, MT), 256>>>(hc, S_SZ, O2_W, Q_SZ, O2_b,
                                      out_coarse, Q_SZ, Q_SZ, S_SZ);
    // 6) out_fine = hf @ O4_W + O4_b
    sgemm128<2><<<dim3(2, MT), 256>>>(hf, S_SZ, O4_W, Q_SZ, O4_b,
                                      out_fine, Q_SZ, Q_SZ, S_SZ);
}

// round 5
// speedup vs baseline: 3.0002x; 3.0002x over previous
#include <cuda_runtime.h>
#include <math.h>
#include <stdint.h>

// Problem dims (fixed)
#define B_SZ 32768
#define H_SZ 896
#define S_SZ 448
#define Q_SZ 256
#define H3   2688
#define S3   1344

// ---------------------------------------------------------------------------
// Scratch (device globals; allocation-free per harness rules)
// ---------------------------------------------------------------------------
__device__ float g_Rh [(size_t)B_SZ * H3];    // R_hidden [B,3H]
__device__ float g_Aq [(size_t)B_SZ * H_SZ];  // tf32-rounded prev_hidden
__device__ float g_hA [(size_t)B_SZ * H_SZ];  // tf32-rounded hidden
__device__ float g_hc [(size_t)B_SZ * S_SZ];
__device__ float g_hf [(size_t)B_SZ * S_SZ];
__device__ float g_RWt[(size_t)H3 * H_SZ];    // R_W transposed+rounded [2688,896]
__device__ float g_O1t[S_SZ * S_SZ];
__device__ float g_O2t[Q_SZ * S_SZ];
__device__ float g_O3t[S_SZ * S_SZ];
__device__ float g_O4t[Q_SZ * S_SZ];

// ---------------------------------------------------------------------------
// Helpers (all non-arch-specific PTX: legal on plain sm_103)
// ---------------------------------------------------------------------------
__device__ __forceinline__ float rna_tf32(float x) {
    float r; asm("cvt.rna.tf32.f32 %0, %1;" : "=f"(r) : "f"(x)); return r;
}
__device__ __forceinline__ uint32_t smem_u32(const void* p) {
    uint32_t a;
    asm("{ .reg .u64 t; cvta.to.shared.u64 t, %1; cvt.u32.u64 %0, t; }" : "=r"(a) : "l"(p));
    return a;
}
__device__ __forceinline__ void cp_async16(uint32_t s, const void* g) {
    asm volatile("cp.async.cg.shared.global [%0], [%1], 16;\n" :: "r"(s), "l"(g));
}
__device__ __forceinline__ void cp_async16_pred(uint32_t s, const void* g, int sz) {
    asm volatile("cp.async.cg.shared.global [%0], [%1], 16, %2;\n"
                 :: "r"(s), "l"(g), "r"(sz));
}
#define CP_COMMIT()  asm volatile("cp.async.commit_group;\n" ::)
#define CP_WAIT(n)   asm volatile("cp.async.wait_group %0;\n" :: "n"(n))

__device__ __forceinline__ void mma_m16n8k8(float* d, const float* a, const float* b) {
    asm volatile(
        "mma.sync.aligned.m16n8k8.row.col.f32.tf32.tf32.f32 "
        "{%0,%1,%2,%3}, {%4,%5,%6,%7}, {%8,%9}, {%0,%1,%2,%3};"
        : "+f"(d[0]), "+f"(d[1]), "+f"(d[2]), "+f"(d[3])
        : "r"(__float_as_uint(a[0])), "r"(__float_as_uint(a[1])),
          "r"(__float_as_uint(a[2])), "r"(__float_as_uint(a[3])),
          "r"(__float_as_uint(b[0])), "r"(__float_as_uint(b[1])));
}

// ---------------------------------------------------------------------------
// mma.sync tf32 GEMM: C[M,N] = A[M,K] @ Bt[N,K]^T (+bias)(+relu+round)
// BM=128, BN=128, BK=16. 256 threads = 8 warps in 2x4, warp tile 64x32.
// M multiple of 128 (32768 ok). K multiple of 16 (896/448 ok). N guarded.
// Inputs pre-rounded to tf32 RNE. EPI: 0=none, 1=bias+relu+round, 2=bias.
// ---------------------------------------------------------------------------
template <int EPI>
__global__ void __launch_bounds__(256, 2)
mgemm(const float* __restrict__ A, int lda,
      const float* __restrict__ Bt, int ldb,
      const float* __restrict__ bias,
      float* __restrict__ C, int ldc, int N, int K)
{
    __shared__ float As[2][128][20];   // 16 K-floats + 4 pad (bank-conflict-free)
    __shared__ float Bs[2][128][20];

    const int tid = threadIdx.x;
    const int lane = tid & 31, w = tid >> 5;
    const int wr = w >> 2, wc = w & 3;       // warp grid 2x4
    const int lq = lane >> 2, ln = lane & 3;

    const int rowBase = blockIdx.y * 128;
    const int colBase = blockIdx.x * 128;

    // cp.async chunk mapping: 512 16B-chunks per tile, 2 per thread
    const int c0r = tid >> 2,        c0c = tid & 3;          // chunk tid
    const int c1r = (tid + 256) >> 2, c1c = (tid + 256) & 3; // chunk tid+256

    const uint32_t sA = smem_u32(&As[0][0][0]);
    const uint32_t sB = smem_u32(&Bs[0][0][0]);
    const uint32_t BUFB = 128 * 20 * 4;      // bytes per buffer

    // B row validity (N guard): clamp pointer row, zero-fill via src-size
    const int bn0 = colBase + c0r, bn1 = colBase + c1r;
    const int bsz0 = (bn0 < N) ? 16 : 0, bsz1 = (bn1 < N) ? 16 : 0;
    const float* Brow0 = Bt + (size_t)(bsz0 ? bn0 : 0) * ldb;
    const float* Brow1 = Bt + (size_t)(bsz1 ? bn1 : 0) * ldb;
    const float* Arow0 = A + (size_t)(rowBase + c0r) * lda;
    const float* Arow1 = A + (size_t)(rowBase + c1r) * lda;

    auto load_tile = [&](int buf, int it) {
        const int kb = it * 16;
        cp_async16(sA + buf * BUFB + (c0r * 20 + c0c * 4) * 4, Arow0 + kb + c0c * 4);
        cp_async16(sA + buf * BUFB + (c1r * 20 + c1c * 4) * 4, Arow1 + kb + c1c * 4);
        cp_async16_pred(sB + buf * BUFB + (c0r * 20 + c0c * 4) * 4, Brow0 + kb + c0c * 4, bsz0);
        cp_async16_pred(sB + buf * BUFB + (c1r * 20 + c1c * 4) * 4, Brow1 + kb + c1c * 4, bsz1);
        CP_COMMIT();
    };

    float acc[4][4][4];
    #pragma unroll
    for (int i = 0; i < 4; ++i)
        #pragma unroll
        for (int j = 0; j < 4; ++j)
            #pragma unroll
            for (int k = 0; k < 4; ++k) acc[i][j][k] = 0.0f;

    const int nit = K >> 4;
    load_tile(0, 0);

    for (int it = 0; it < nit; ++it) {
        const int buf = it & 1;
        if (it + 1 < nit) { load_tile(buf ^ 1, it + 1); CP_WAIT(1); }
        else              { CP_WAIT(0); }
        __syncthreads();

        #pragma unroll
        for (int s = 0; s < 2; ++s) {
            const int k0 = s * 8;
            float a[4][4], b[4][2];
            #pragma unroll
            for (int mf = 0; mf < 4; ++mf) {
                const int m = wr * 64 + mf * 16 + lq;
                a[mf][0] = As[buf][m][k0 + ln];
                a[mf][1] = As[buf][m + 8][k0 + ln];
                a[mf][2] = As[buf][m][k0 + ln + 4];
                a[mf][3] = As[buf][m + 8][k0 + ln + 4];
            }
            #pragma unroll
            for (int nf = 0; nf < 4; ++nf) {
                const int n = wc * 32 + nf * 8 + lq;
                b[nf][0] = Bs[buf][n][k0 + ln];
                b[nf][1] = Bs[buf][n][k0 + ln + 4];
            }
            #pragma unroll
            for (int mf = 0; mf < 4; ++mf)
                #pragma unroll
                for (int nf = 0; nf < 4; ++nf)
                    mma_m16n8k8(acc[mf][nf], a[mf], b[nf]);
        }
        __syncthreads();
    }

    // ---- epilogue: direct STG.64 (quad-contiguous 32B sectors) ----
    #pragma unroll
    for (int nf = 0; nf < 4; ++nf) {
        const int col = colBase + wc * 32 + nf * 8 + ln * 2;
        if (col < N) {
            float2 bv = make_float2(0.0f, 0.0f);
            if (EPI) bv = *reinterpret_cast<const float2*>(bias + col);
            #pragma unroll
            for (int mf = 0; mf < 4; ++mf) {
                const int row = rowBase + wr * 64 + mf * 16 + lq;
                float2 v0 = make_float2(acc[mf][nf][0], acc[mf][nf][1]);
                float2 v1 = make_float2(acc[mf][nf][2], acc[mf][nf][3]);
                if (EPI) {
                    v0.x += bv.x; v0.y += bv.y; v1.x += bv.x; v1.y += bv.y;
                    if (EPI == 1) {
                        v0.x = rna_tf32(fmaxf(v0.x, 0.0f));
                        v0.y = rna_tf32(fmaxf(v0.y, 0.0f));
                        v1.x = rna_tf32(fmaxf(v1.x, 0.0f));
                        v1.y = rna_tf32(fmaxf(v1.y, 0.0f));
                    }
                }
                *reinterpret_cast<float2*>(C + (size_t)row * ldc + col) = v0;
                *reinterpret_cast<float2*>(C + (size_t)(row + 8) * ldc + col) = v1;
            }
        }
    }
}

// ---------------------------------------------------------------------------
// Prep kernels: RNE tf32 rounding (+ transpose for weights)
// ---------------------------------------------------------------------------
__global__ void round_copy(const float4* __restrict__ in, float4* __restrict__ out, int n4) {
    int i = blockIdx.x * blockDim.x + threadIdx.x;
    if (i < n4) {
        float4 v = in[i];
        v.x = rna_tf32(v.x); v.y = rna_tf32(v.y);
        v.z = rna_tf32(v.z); v.w = rna_tf32(v.w);
        out[i] = v;
    }
}

// in [K,N] row-major -> out [N,K] row-major, rounded. K,N multiples of 32.
__global__ void transpose_round(const float* __restrict__ in, float* __restrict__ out,
                                int K, int N) {
    __shared__ float t[32][33];
    const int n0 = blockIdx.x * 32, k0 = blockIdx.y * 32;
    const int tx = threadIdx.x, ty = threadIdx.y;   // 32 x 8
    #pragma unroll
    for (int j = 0; j < 32; j += 8)
        t[ty + j][tx] = rna_tf32(in[(size_t)(k0 + ty + j) * N + n0 + tx]);
    __syncthreads();
    #pragma unroll
    for (int j = 0; j < 32; j += 8)
        out[(size_t)(n0 + ty + j) * K + k0 + tx] = t[tx][ty + j];
}

// ---------------------------------------------------------------------------
// GRU gate elementwise (folds tiny input projections); emits rounded copy too
// ---------------------------------------------------------------------------
__global__ void gru_elem(const float* __restrict__ Rh, const float* __restrict__ prev_h,
                         const float* __restrict__ prev_y, const float* __restrict__ ccoarse,
                         const float* __restrict__ Icw, const float* __restrict__ Ifw,
                         const float* __restrict__ bu, const float* __restrict__ br,
                         const float* __restrict__ be,
                         float* __restrict__ hidden, float* __restrict__ hA) {
    const int idx = blockIdx.x * blockDim.x + threadIdx.x;
    if (idx >= B_SZ * H_SZ) return;
    const int b = idx / H_SZ;
    const int h = idx - b * H_SZ;

    const float py0 = prev_y[2 * b], py1 = prev_y[2 * b + 1];
    float Iu, Ir, Ie;
    if (h < S_SZ) {
        Iu = py0 * Icw[h]            + py1 * Icw[S3 + h];
        Ir = py0 * Icw[S_SZ + h]     + py1 * Icw[S3 + S_SZ + h];
        Ie = py0 * Icw[2 * S_SZ + h] + py1 * Icw[S3 + 2 * S_SZ + h];
    } else {
        const int hh = h - S_SZ;
        const float cc = ccoarse[b];
        Iu = py0 * Ifw[hh]            + py1 * Ifw[S3 + hh]            + cc * Ifw[2 * S3 + hh];
        Ir = py0 * Ifw[S_SZ + hh]     + py1 * Ifw[S3 + S_SZ + hh]     + cc * Ifw[2 * S3 + S_SZ + hh];
        Ie = py0 * Ifw[2 * S_SZ + hh] + py1 * Ifw[S3 + 2 * S_SZ + hh] + cc * Ifw[2 * S3 + 2 * S_SZ + hh];
    }
    const float* r0 = Rh + (size_t)b * H3;
    const float Ru = r0[h], Rr = r0[H_SZ + h], Re = r0[2 * H_SZ + h];

    const float u = 1.0f / (1.0f + expf(-(Ru + Iu + bu[h])));
    const float r = 1.0f / (1.0f + expf(-(Rr + Ir + br[h])));
    const float e = tanhf(r * Re + Ie + be[h]);

    const float hv = u * prev_h[idx] + (1.0f - u) * e;
    hidden[idx] = hv;
    hA[idx] = rna_tf32(hv);
}

// ---------------------------------------------------------------------------
// Launch
// ---------------------------------------------------------------------------
extern "C" void kernel_launch(void* const* d_in, const int* in_sizes, int n_in,
                              void* d_out, int out_size)
{
    const float* prev_y  = (const float*)d_in[0];
    const float* prev_h  = (const float*)d_in[1];
    const float* ccoarse = (const float*)d_in[2];
    const float* R_W     = (const float*)d_in[3];
    const float* Icw     = (const float*)d_in[4];
    const float* Ifw     = (const float*)d_in[5];
    const float* O1_W    = (const float*)d_in[6];
    const float* O1_b    = (const float*)d_in[7];
    const float* O2_W    = (const float*)d_in[8];
    const float* O2_b    = (const float*)d_in[9];
    const float* O3_W    = (const float*)d_in[10];
    const float* O3_b    = (const float*)d_in[11];
    const float* O4_W    = (const float*)d_in[12];
    const float* O4_b    = (const float*)d_in[13];
    const float* bu      = (const float*)d_in[14];
    const float* br      = (const float*)d_in[15];
    const float* be      = (const float*)d_in[16];

    float* out        = (float*)d_out;
    float* out_coarse = out;
    float* out_fine   = out + (size_t)B_SZ * Q_SZ;
    float* hidden     = out + (size_t)2 * B_SZ * Q_SZ;

    float *Rh, *Aq, *hA, *hc, *hf, *RWt, *O1t, *O2t, *O3t, *O4t;
    cudaGetSymbolAddress((void**)&Rh,  g_Rh);
    cudaGetSymbolAddress((void**)&Aq,  g_Aq);
    cudaGetSymbolAddress((void**)&hA,  g_hA);
    cudaGetSymbolAddress((void**)&hc,  g_hc);
    cudaGetSymbolAddress((void**)&hf,  g_hf);
    cudaGetSymbolAddress((void**)&RWt, g_RWt);
    cudaGetSymbolAddress((void**)&O1t, g_O1t);
    cudaGetSymbolAddress((void**)&O2t, g_O2t);
    cudaGetSymbolAddress((void**)&O3t, g_O3t);
    cudaGetSymbolAddress((void**)&O4t, g_O4t);

    // --- prep: RNE tf32 rounding (+ weight transpose) ---
    const int n4 = B_SZ * H_SZ / 4;
    round_copy<<<n4 / 256, 256>>>((const float4*)prev_h, (float4*)Aq, n4);
    transpose_round<<<dim3(H3 / 32, H_SZ / 32), dim3(32, 8)>>>(R_W, RWt, H_SZ, H3);
    transpose_round<<<dim3(S_SZ / 32, S_SZ / 32), dim3(32, 8)>>>(O1_W, O1t, S_SZ, S_SZ);
    transpose_round<<<dim3(Q_SZ / 32, S_SZ / 32), dim3(32, 8)>>>(O2_W, O2t, S_SZ, Q_SZ);
    transpose_round<<<dim3(S_SZ / 32, S_SZ / 32), dim3(32, 8)>>>(O3_W, O3t, S_SZ, S_SZ);
    transpose_round<<<dim3(Q_SZ / 32, S_SZ / 32), dim3(32, 8)>>>(O4_W, O4t, S_SZ, Q_SZ);

    const int MT = B_SZ / 128;   // 256 M-tiles

    // 1) Rh = Aq @ RWt^T   [32768,896] x [2688,896]^T
    mgemm<0><<<dim3(H3 / 128, MT), 256>>>(Aq, H_SZ, RWt, H_SZ, nullptr,
                                          Rh, H3, H3, H_SZ);
    // 2) GRU gates -> hidden (fp32) + rounded copy
    gru_elem<<<(B_SZ * H_SZ + 255) / 256, 256>>>(Rh, prev_h, prev_y, ccoarse,
                                                 Icw, Ifw, bu, br, be, hidden, hA);
    // 3) hc = round(relu(hidden_c @ O1 + b1))   N=448 -> 4 tiles (guarded)
    mgemm<1><<<dim3(4, MT), 256>>>(hA, H_SZ, O1t, S_SZ, O1_b, hc, S_SZ, S_SZ, S_SZ);
    // 4) hf = round(relu(hidden_f @ O3 + b3))
    mgemm<1><<<dim3(4, MT), 256>>>(hA + S_SZ, H_SZ, O3t, S_SZ, O3_b, hf, S_SZ, S_SZ, S_SZ);
    // 5) out_coarse = hc @ O2 + b2   N=256
    mgemm<2><<<dim3(2, MT), 256>>>(hc, S_SZ, O2t, S_SZ, O2_b, out_coarse, Q_SZ, Q_SZ, S_SZ);
    // 6) out_fine = hf @ O4 + b4
    mgemm<2><<<dim3(2, MT), 256>>>(hf, S_SZ, O4t, S_SZ, O4_b, out_fine, Q_SZ, Q_SZ, S_SZ);
}

// round 7
// speedup vs baseline: 3.2121x; 1.0706x over previous
#include <cuda_runtime.h>
#include <math.h>
#include <stdint.h>

// Problem dims (fixed)
#define B_SZ 32768
#define H_SZ 896
#define S_SZ 448
#define Q_SZ 256
#define H3   2688
#define S3   1344

// ---------------------------------------------------------------------------
// Scratch (device globals; allocation-free per harness rules)
// ---------------------------------------------------------------------------
__device__ float g_Rh [(size_t)B_SZ * H3];    // R_hidden [B,3H]
__device__ float g_hc [(size_t)B_SZ * S_SZ];
__device__ float g_hf [(size_t)B_SZ * S_SZ];
__device__ float g_RWt[(size_t)H3 * H_SZ];    // R_W transposed+rounded
__device__ float g_O1t[S_SZ * S_SZ];
__device__ float g_O2t[Q_SZ * S_SZ];
__device__ float g_O3t[S_SZ * S_SZ];
__device__ float g_O4t[Q_SZ * S_SZ];

// ---------------------------------------------------------------------------
// Helpers (non-arch-specific PTX only: must assemble for plain sm_103)
// ---------------------------------------------------------------------------
__device__ __forceinline__ float rna_tf32(float x) {
    float r; asm("cvt.rna.tf32.f32 %0, %1;" : "=f"(r) : "f"(x)); return r;
}
__device__ __forceinline__ uint32_t smem_u32(const void* p) {
    uint32_t a;
    asm("{ .reg .u64 t; cvta.to.shared.u64 t, %1; cvt.u32.u64 %0, t; }" : "=r"(a) : "l"(p));
    return a;
}
__device__ __forceinline__ void cp_async16(uint32_t s, const void* g) {
    asm volatile("cp.async.cg.shared.global [%0], [%1], 16;\n" :: "r"(s), "l"(g));
}
__device__ __forceinline__ void cp_async16_pred(uint32_t s, const void* g, int sz) {
    asm volatile("cp.async.cg.shared.global [%0], [%1], 16, %2;\n"
                 :: "r"(s), "l"(g), "r"(sz));
}
#define CP_COMMIT()  asm volatile("cp.async.commit_group;\n" ::)
#define CP_WAIT(n)   asm volatile("cp.async.wait_group %0;\n" :: "n"(n))

__device__ __forceinline__ void mma_m16n8k8(float* d, const float* a, const float* b) {
    asm volatile(
        "mma.sync.aligned.m16n8k8.row.col.f32.tf32.tf32.f32 "
        "{%0,%1,%2,%3}, {%4,%5,%6,%7}, {%8,%9}, {%0,%1,%2,%3};"
        : "+f"(d[0]), "+f"(d[1]), "+f"(d[2]), "+f"(d[3])
        : "r"(__float_as_uint(a[0])), "r"(__float_as_uint(a[1])),
          "r"(__float_as_uint(a[2])), "r"(__float_as_uint(a[3])),
          "r"(__float_as_uint(b[0])), "r"(__float_as_uint(b[1])));
}

// ---------------------------------------------------------------------------
// mma.sync tf32 GEMM: C[M,N] = A[M,K] @ Bt[N,K]^T (+bias)(+relu+round)
// BM=128, BN=128, BK=32, double-buffered cp.async, 256 thr = 8 warps (2x4),
// warp tile 64x32. Bt pre-rounded; A rounded in-kernel when RND_A=1.
// EPI: 0=none, 1=bias+relu+round, 2=bias.
// ---------------------------------------------------------------------------
#define PITCH 36                     // 32 + 4 pad: LDS pattern hits all 32 banks
#define TILEB (128 * PITCH * 4)      // bytes per matrix per buffer (18432)

template <int EPI, int RND_A>
__global__ void __launch_bounds__(256, 2)
mgemm(const float* __restrict__ A, int lda,
      const float* __restrict__ Bt, int ldb,
      const float* __restrict__ bias,
      float* __restrict__ C, int ldc, int N, int K)
{
    extern __shared__ float smem[];  // [2 buf][2 mat][128][PITCH]
    float* Asm = smem;               // buf b at offset b*2*128*PITCH
    float* Bsm = smem + 128 * PITCH;

    const int tid = threadIdx.x;
    const int lane = tid & 31, w = tid >> 5;
    const int wr = w >> 2, wc = w & 3;        // warp grid 2x4
    const int lq = lane >> 2, ln = lane & 3;

    const int rowBase = blockIdx.y * 128;
    const int colBase = blockIdx.x * 128;

    const uint32_t sA = smem_u32(Asm);
    const uint32_t sB = smem_u32(Bsm);
    const uint32_t BUFB = 2u * TILEB;         // stride between buffers

    // cp.async mapping: 1024 16B-chunks per matrix per iter, 4 per thread.
    // chunk c: row = c>>3 (8 chunks/row of 32 floats), col16 = c&7
    int arow[4], brow[4], acol[4];
    int bsz[4];
    const float *Ar[4], *Br[4];
    #pragma unroll
    for (int i = 0; i < 4; ++i) {
        const int c = tid + i * 256;
        arow[i] = c >> 3; acol[i] = c & 7;
        brow[i] = arow[i];
        const int bn = colBase + brow[i];
        bsz[i] = (bn < N) ? 16 : 0;
        Ar[i] = A + (size_t)(rowBase + arow[i]) * lda + acol[i] * 4;
        Br[i] = Bt + (size_t)(bsz[i] ? bn : 0) * ldb + acol[i] * 4;
    }

    auto load_tile = [&](int buf, int it) {
        const int kb = it * 32;
        #pragma unroll
        for (int i = 0; i < 4; ++i)
            cp_async16(sA + buf * BUFB + (arow[i] * PITCH + acol[i] * 4) * 4, Ar[i] + kb);
        #pragma unroll
        for (int i = 0; i < 4; ++i)
            cp_async16_pred(sB + buf * BUFB + (brow[i] * PITCH + acol[i] * 4) * 4, Br[i] + kb, bsz[i]);
        CP_COMMIT();
    };

    float acc[4][4][4];
    #pragma unroll
    for (int i = 0; i < 4; ++i)
        #pragma unroll
        for (int j = 0; j < 4; ++j)
            #pragma unroll
            for (int k = 0; k < 4; ++k) acc[i][j][k] = 0.0f;

    const int nit = K >> 5;
    load_tile(0, 0);

    for (int it = 0; it < nit; ++it) {
        const int buf = it & 1;
        if (it + 1 < nit) { load_tile(buf ^ 1, it + 1); CP_WAIT(1); }
        else              { CP_WAIT(0); }
        __syncthreads();

        const float* Ab = Asm + buf * 2 * 128 * PITCH;
        const float* Bb = Bsm + buf * 2 * 128 * PITCH;

        #pragma unroll
        for (int s = 0; s < 4; ++s) {
            const int k0 = s * 8;
            float a[4][4], b[4][2];
            #pragma unroll
            for (int mf = 0; mf < 4; ++mf) {
                const int m = wr * 64 + mf * 16 + lq;
                a[mf][0] = Ab[m * PITCH + k0 + ln];
                a[mf][1] = Ab[(m + 8) * PITCH + k0 + ln];
                a[mf][2] = Ab[m * PITCH + k0 + ln + 4];
                a[mf][3] = Ab[(m + 8) * PITCH + k0 + ln + 4];
                if (RND_A) {
                    a[mf][0] = rna_tf32(a[mf][0]);
                    a[mf][1] = rna_tf32(a[mf][1]);
                    a[mf][2] = rna_tf32(a[mf][2]);
                    a[mf][3] = rna_tf32(a[mf][3]);
                }
            }
            #pragma unroll
            for (int nf = 0; nf < 4; ++nf) {
                const int n = wc * 32 + nf * 8 + lq;
                b[nf][0] = Bb[n * PITCH + k0 + ln];
                b[nf][1] = Bb[n * PITCH + k0 + ln + 4];
            }
            #pragma unroll
            for (int mf = 0; mf < 4; ++mf)
                #pragma unroll
                for (int nf = 0; nf < 4; ++nf)
                    mma_m16n8k8(acc[mf][nf], a[mf], b[nf]);
        }
        __syncthreads();
    }

    // ---- epilogue: direct STG.64 ----
    #pragma unroll
    for (int nf = 0; nf < 4; ++nf) {
        const int col = colBase + wc * 32 + nf * 8 + ln * 2;
        if (col < N) {
            float2 bv = make_float2(0.0f, 0.0f);
            if (EPI) bv = *reinterpret_cast<const float2*>(bias + col);
            #pragma unroll
            for (int mf = 0; mf < 4; ++mf) {
                const int row = rowBase + wr * 64 + mf * 16 + lq;
                float2 v0 = make_float2(acc[mf][nf][0], acc[mf][nf][1]);
                float2 v1 = make_float2(acc[mf][nf][2], acc[mf][nf][3]);
                if (EPI) {
                    v0.x += bv.x; v0.y += bv.y; v1.x += bv.x; v1.y += bv.y;
                    if (EPI == 1) {
                        v0.x = rna_tf32(fmaxf(v0.x, 0.0f));
                        v0.y = rna_tf32(fmaxf(v0.y, 0.0f));
                        v1.x = rna_tf32(fmaxf(v1.x, 0.0f));
                        v1.y = rna_tf32(fmaxf(v1.y, 0.0f));
                    }
                }
                *reinterpret_cast<float2*>(C + (size_t)row * ldc + col) = v0;
                *reinterpret_cast<float2*>(C + (size_t)(row + 8) * ldc + col) = v1;
            }
        }
    }
}

// ---------------------------------------------------------------------------
// Weight prep: [K,N] row-major -> [N,K] row-major, tf32-RNE rounded
// ---------------------------------------------------------------------------
__global__ void transpose_round(const float* __restrict__ in, float* __restrict__ out,
                                int K, int N) {
    __shared__ float t[32][33];
    const int n0 = blockIdx.x * 32, k0 = blockIdx.y * 32;
    const int tx = threadIdx.x, ty = threadIdx.y;   // 32 x 8
    #pragma unroll
    for (int j = 0; j < 32; j += 8)
        t[ty + j][tx] = rna_tf32(in[(size_t)(k0 + ty + j) * N + n0 + tx]);
    __syncthreads();
    #pragma unroll
    for (int j = 0; j < 32; j += 8)
        out[(size_t)(n0 + ty + j) * K + k0 + tx] = t[tx][ty + j];
}

// ---------------------------------------------------------------------------
// GRU gate elementwise (folds tiny input projections)
// ---------------------------------------------------------------------------
__global__ void gru_elem(const float* __restrict__ Rh, const float* __restrict__ prev_h,
                         const float* __restrict__ prev_y, const float* __restrict__ ccoarse,
                         const float* __restrict__ Icw, const float* __restrict__ Ifw,
                         const float* __restrict__ bu, const float* __restrict__ br,
                         const float* __restrict__ be,
                         float* __restrict__ hidden) {
    const int idx = blockIdx.x * blockDim.x + threadIdx.x;
    if (idx >= B_SZ * H_SZ) return;
    const int b = idx / H_SZ;
    const int h = idx - b * H_SZ;

    const float py0 = prev_y[2 * b], py1 = prev_y[2 * b + 1];
    float Iu, Ir, Ie;
    if (h < S_SZ) {
        Iu = py0 * Icw[h]            + py1 * Icw[S3 + h];
        Ir = py0 * Icw[S_SZ + h]     + py1 * Icw[S3 + S_SZ + h];
        Ie = py0 * Icw[2 * S_SZ + h] + py1 * Icw[S3 + 2 * S_SZ + h];
    } else {
        const int hh = h - S_SZ;
        const float cc = ccoarse[b];
        Iu = py0 * Ifw[hh]            + py1 * Ifw[S3 + hh]            + cc * Ifw[2 * S3 + hh];
        Ir = py0 * Ifw[S_SZ + hh]     + py1 * Ifw[S3 + S_SZ + hh]     + cc * Ifw[2 * S3 + S_SZ + hh];
        Ie = py0 * Ifw[2 * S_SZ + hh] + py1 * Ifw[S3 + 2 * S_SZ + hh] + cc * Ifw[2 * S3 + 2 * S_SZ + hh];
    }
    const float* r0 = Rh + (size_t)b * H3;
    const float Ru = r0[h], Rr = r0[H_SZ + h], Re = r0[2 * H_SZ + h];

    const float u = 1.0f / (1.0f + expf(-(Ru + Iu + bu[h])));
    const float r = 1.0f / (1.0f + expf(-(Rr + Ir + br[h])));
    const float e = tanhf(r * Re + Ie + be[h]);

    hidden[idx] = u * prev_h[idx] + (1.0f - u) * e;
}

// ---------------------------------------------------------------------------
// Launch
// ---------------------------------------------------------------------------
extern "C" void kernel_launch(void* const* d_in, const int* in_sizes, int n_in,
                              void* d_out, int out_size)
{
    const float* prev_y  = (const float*)d_in[0];
    const float* prev_h  = (const float*)d_in[1];
    const float* ccoarse = (const float*)d_in[2];
    const float* R_W     = (const float*)d_in[3];
    const float* Icw     = (const float*)d_in[4];
    const float* Ifw     = (const float*)d_in[5];
    const float* O1_W    = (const float*)d_in[6];
    const float* O1_b    = (const float*)d_in[7];
    const float* O2_W    = (const float*)d_in[8];
    const float* O2_b    = (const float*)d_in[9];
    const float* O3_W    = (const float*)d_in[10];
    const float* O3_b    = (const float*)d_in[11];
    const float* O4_W    = (const float*)d_in[12];
    const float* O4_b    = (const float*)d_in[13];
    const float* bu      = (const float*)d_in[14];
    const float* br      = (const float*)d_in[15];
    const float* be      = (const float*)d_in[16];

    float* out        = (float*)d_out;
    float* out_coarse = out;
    float* out_fine   = out + (size_t)B_SZ * Q_SZ;
    float* hidden     = out + (size_t)2 * B_SZ * Q_SZ;

    float *Rh, *hc, *hf, *RWt, *O1t, *O2t, *O3t, *O4t;
    cudaGetSymbolAddress((void**)&Rh,  g_Rh);
    cudaGetSymbolAddress((void**)&hc,  g_hc);
    cudaGetSymbolAddress((void**)&hf,  g_hf);
    cudaGetSymbolAddress((void**)&RWt, g_RWt);
    cudaGetSymbolAddress((void**)&O1t, g_O1t);
    cudaGetSymbolAddress((void**)&O2t, g_O2t);
    cudaGetSymbolAddress((void**)&O3t, g_O3t);
    cudaGetSymbolAddress((void**)&O4t, g_O4t);

    const int SMB = 4 * 128 * PITCH * 4;   // 73728 bytes dynamic smem
    cudaFuncSetAttribute(mgemm<0, 1>, cudaFuncAttributeMaxDynamicSharedMemorySize, SMB);
    cudaFuncSetAttribute(mgemm<1, 1>, cudaFuncAttributeMaxDynamicSharedMemorySize, SMB);
    cudaFuncSetAttribute(mgemm<2, 0>, cudaFuncAttributeMaxDynamicSharedMemorySize, SMB);

    // --- weight prep: transpose + RNE tf32 round (tiny) ---
    transpose_round<<<dim3(H3 / 32, H_SZ / 32), dim3(32, 8)>>>(R_W, RWt, H_SZ, H3);
    transpose_round<<<dim3(S_SZ / 32, S_SZ / 32), dim3(32, 8)>>>(O1_W, O1t, S_SZ, S_SZ);
    transpose_round<<<dim3(Q_SZ / 32, S_SZ / 32), dim3(32, 8)>>>(O2_W, O2t, S_SZ, Q_SZ);
    transpose_round<<<dim3(S_SZ / 32, S_SZ / 32), dim3(32, 8)>>>(O3_W, O3t, S_SZ, S_SZ);
    transpose_round<<<dim3(Q_SZ / 32, S_SZ / 32), dim3(32, 8)>>>(O4_W, O4t, S_SZ, Q_SZ);

    const int MT = B_SZ / 128;   // 256 M-tiles

    // 1) Rh = round(prev_h) @ RWt^T   [32768,896] x [2688,896]^T
    mgemm<0, 1><<<dim3(H3 / 128, MT), 256, SMB>>>(prev_h, H_SZ, RWt, H_SZ, nullptr,
                                                  Rh, H3, H3, H_SZ);
    // 2) GRU gates -> hidden (fp32, exact output)
    gru_elem<<<(B_SZ * H_SZ + 255) / 256, 256>>>(Rh, prev_h, prev_y, ccoarse,
                                                 Icw, Ifw, bu, br, be, hidden);
    // 3) hc = round(relu(hidden_c @ O1 + b1))   N=448
    mgemm<1, 1><<<dim3(4, MT), 256, SMB>>>(hidden, H_SZ, O1t, S_SZ, O1_b,
                                           hc, S_SZ, S_SZ, S_SZ);
    // 4) hf = round(relu(hidden_f @ O3 + b3))
    mgemm<1, 1><<<dim3(4, MT), 256, SMB>>>(hidden + S_SZ, H_SZ, O3t, S_SZ, O3_b,
                                           hf, S_SZ, S_SZ, S_SZ);
    // 5) out_coarse = hc @ O2 + b2   (hc already tf32-rounded by epilogue)
    mgemm<2, 0><<<dim3(2, MT), 256, SMB>>>(hc, S_SZ, O2t, S_SZ, O2_b,
                                           out_coarse, Q_SZ, Q_SZ, S_SZ);
    // 6) out_fine = hf @ O4 + b4
    mgemm<2, 0><<<dim3(2, MT), 256, SMB>>>(hf, S_SZ, O4t, S_SZ, O4_b,
                                           out_fine, Q_SZ, Q_SZ, S_SZ);
}

// round 8
// speedup vs baseline: 3.3447x; 1.0413x over previous
#include <cuda_runtime.h>
#include <math.h>
#include <stdint.h>

// Problem dims (fixed)
#define B_SZ 32768
#define H_SZ 896
#define S_SZ 448
#define Q_SZ 256
#define H3   2688
#define S3   1344

// ---------------------------------------------------------------------------
// Scratch (device globals; allocation-free per harness rules)
// ---------------------------------------------------------------------------
__device__ float g_Rh [(size_t)B_SZ * H3];
__device__ float g_hc [(size_t)B_SZ * S_SZ];
__device__ float g_hf [(size_t)B_SZ * S_SZ];
__device__ float g_RWt[(size_t)H3 * H_SZ];
__device__ float g_O1t[S_SZ * S_SZ];
__device__ float g_O2t[Q_SZ * S_SZ];
__device__ float g_O3t[S_SZ * S_SZ];
__device__ float g_O4t[Q_SZ * S_SZ];

// ---------------------------------------------------------------------------
// Helpers (non-arch-specific PTX only: must assemble for plain sm_103)
// ---------------------------------------------------------------------------
__device__ __forceinline__ float rna_tf32(float x) {
    float r; asm("cvt.rna.tf32.f32 %0, %1;" : "=f"(r) : "f"(x)); return r;
}
__device__ __forceinline__ uint32_t smem_u32(const void* p) {
    uint32_t a;
    asm("{ .reg .u64 t; cvta.to.shared.u64 t, %1; cvt.u32.u64 %0, t; }" : "=r"(a) : "l"(p));
    return a;
}
__device__ __forceinline__ void cp_async16(uint32_t s, const void* g) {
    asm volatile("cp.async.cg.shared.global [%0], [%1], 16;\n" :: "r"(s), "l"(g));
}
__device__ __forceinline__ void cp_async16_pred(uint32_t s, const void* g, int sz) {
    asm volatile("cp.async.cg.shared.global [%0], [%1], 16, %2;\n"
                 :: "r"(s), "l"(g), "r"(sz));
}
#define CP_COMMIT()  asm volatile("cp.async.commit_group;\n" ::)
#define CP_WAIT(n)   asm volatile("cp.async.wait_group %0;\n" :: "n"(n))

__device__ __forceinline__ void mma_m16n8k8(float* d, const float* a, const float* b) {
    asm volatile(
        "mma.sync.aligned.m16n8k8.row.col.f32.tf32.tf32.f32 "
        "{%0,%1,%2,%3}, {%4,%5,%6,%7}, {%8,%9}, {%0,%1,%2,%3};"
        : "+f"(d[0]), "+f"(d[1]), "+f"(d[2]), "+f"(d[3])
        : "r"(__float_as_uint(a[0])), "r"(__float_as_uint(a[1])),
          "r"(__float_as_uint(a[2])), "r"(__float_as_uint(a[3])),
          "r"(__float_as_uint(b[0])), "r"(__float_as_uint(b[1])));
}

// ---------------------------------------------------------------------------
// mma.sync tf32 GEMM: C[M,N] = A[M,K] @ Bt[N,K]^T (+bias)(+relu+round)
// CTA tile 128x128, BK=32, 128 threads = 4 warps in 2x2, warp tile 64x64.
// Dual-problem mode: blockIdx.z selects (A,Bt,bias,C) set (DUAL=1).
// EPI: 0=none, 1=bias+relu+round, 2=bias.  RND_A: round A after LDS.
// ---------------------------------------------------------------------------
#define PITCH 36
#define MATB  (128 * PITCH * 4)      // bytes per matrix per buffer

template <int EPI, int RND_A, int DUAL>
__global__ void __launch_bounds__(128, 2)
mgemm(const float* __restrict__ A0, const float* __restrict__ A1, int lda,
      const float* __restrict__ B0, const float* __restrict__ B1, int ldb,
      const float* __restrict__ bias0, const float* __restrict__ bias1,
      float* __restrict__ C0, float* __restrict__ C1, int ldc, int N, int K)
{
    extern __shared__ float smem[];  // [2 buf][A|B][128][PITCH]
    const float* A    = (DUAL && blockIdx.z) ? A1 : A0;
    const float* Bt   = (DUAL && blockIdx.z) ? B1 : B0;
    const float* bias = (DUAL && blockIdx.z) ? bias1 : bias0;
    float*       C    = (DUAL && blockIdx.z) ? C1 : C0;

    const int tid = threadIdx.x;
    const int lane = tid & 31, w = tid >> 5;
    const int wr = w >> 1, wc = w & 1;        // warp grid 2x2, warp tile 64x64
    const int lq = lane >> 2, ln = lane & 3;

    const int rowBase = blockIdx.y * 128;
    const int colBase = blockIdx.x * 128;

    const uint32_t sA = smem_u32(smem);
    const uint32_t sB = sA + (uint32_t)MATB;
    const uint32_t BUFB = 2u * MATB;

    // cp.async mapping: 1024 chunks/matrix/iter, 8 per thread.
    // chunk c = tid + i*128: row = (tid>>3) + 16*i, col16 = tid&7 (fixed).
    const int r0 = tid >> 3, c16 = tid & 7;
    const float* Abase = A + (size_t)(rowBase + r0) * lda + c16 * 4;
    const uint32_t dstOffA = (uint32_t)((r0 * PITCH + c16 * 4) * 4);

    auto load_tile = [&](int buf, int it) {
        const int kb = it * 32;
        #pragma unroll
        for (int i = 0; i < 8; ++i)
            cp_async16(sA + buf * BUFB + dstOffA + (uint32_t)(i * 16 * PITCH * 4),
                       Abase + kb + (size_t)(i * 16) * lda);
        #pragma unroll
        for (int i = 0; i < 8; ++i) {
            const int bn = colBase + r0 + 16 * i;
            const int sz = (bn < N) ? 16 : 0;
            const float* gp = Bt + (size_t)(sz ? bn : 0) * ldb + c16 * 4 + kb;
            cp_async16_pred(sB + buf * BUFB + dstOffA + (uint32_t)(i * 16 * PITCH * 4), gp, sz);
        }
        CP_COMMIT();
    };

    float acc[4][8][4];
    #pragma unroll
    for (int i = 0; i < 4; ++i)
        #pragma unroll
        for (int j = 0; j < 8; ++j)
            #pragma unroll
            for (int k = 0; k < 4; ++k) acc[i][j][k] = 0.0f;

    const int nit = K >> 5;
    load_tile(0, 0);

    for (int it = 0; it < nit; ++it) {
        const int buf = it & 1;
        if (it + 1 < nit) { load_tile(buf ^ 1, it + 1); CP_WAIT(1); }
        else              { CP_WAIT(0); }
        __syncthreads();

        const float* Ab = smem + buf * (2 * 128 * PITCH);
        const float* Bb = Ab + 128 * PITCH;

        #pragma unroll
        for (int s = 0; s < 4; ++s) {
            const int k0 = s * 8;
            float a[4][4], b[8][2];
            #pragma unroll
            for (int mf = 0; mf < 4; ++mf) {
                const int m = wr * 64 + mf * 16 + lq;
                a[mf][0] = Ab[m * PITCH + k0 + ln];
                a[mf][1] = Ab[(m + 8) * PITCH + k0 + ln];
                a[mf][2] = Ab[m * PITCH + k0 + ln + 4];
                a[mf][3] = Ab[(m + 8) * PITCH + k0 + ln + 4];
                if (RND_A) {
                    a[mf][0] = rna_tf32(a[mf][0]);
                    a[mf][1] = rna_tf32(a[mf][1]);
                    a[mf][2] = rna_tf32(a[mf][2]);
                    a[mf][3] = rna_tf32(a[mf][3]);
                }
            }
            #pragma unroll
            for (int nf = 0; nf < 8; ++nf) {
                const int n = wc * 64 + nf * 8 + lq;
                b[nf][0] = Bb[n * PITCH + k0 + ln];
                b[nf][1] = Bb[n * PITCH + k0 + ln + 4];
            }
            #pragma unroll
            for (int mf = 0; mf < 4; ++mf)
                #pragma unroll
                for (int nf = 0; nf < 8; ++nf)
                    mma_m16n8k8(acc[mf][nf], a[mf], b[nf]);
        }
        __syncthreads();
    }

    // ---- epilogue: direct STG.64 ----
    #pragma unroll
    for (int nf = 0; nf < 8; ++nf) {
        const int col = colBase + wc * 64 + nf * 8 + ln * 2;
        if (col < N) {
            float2 bv = make_float2(0.0f, 0.0f);
            if (EPI) bv = *reinterpret_cast<const float2*>(bias + col);
            #pragma unroll
            for (int mf = 0; mf < 4; ++mf) {
                const int row = rowBase + wr * 64 + mf * 16 + lq;
                float2 v0 = make_float2(acc[mf][nf][0], acc[mf][nf][1]);
                float2 v1 = make_float2(acc[mf][nf][2], acc[mf][nf][3]);
                if (EPI) {
                    v0.x += bv.x; v0.y += bv.y; v1.x += bv.x; v1.y += bv.y;
                    if (EPI == 1) {
                        v0.x = rna_tf32(fmaxf(v0.x, 0.0f));
                        v0.y = rna_tf32(fmaxf(v0.y, 0.0f));
                        v1.x = rna_tf32(fmaxf(v1.x, 0.0f));
                        v1.y = rna_tf32(fmaxf(v1.y, 0.0f));
                    }
                }
                *reinterpret_cast<float2*>(C + (size_t)row * ldc + col) = v0;
                *reinterpret_cast<float2*>(C + (size_t)(row + 8) * ldc + col) = v1;
            }
        }
    }
}

// ---------------------------------------------------------------------------
// Weight prep: [K,N] row-major -> [N,K] row-major, tf32-RNE rounded
// ---------------------------------------------------------------------------
__global__ void transpose_round(const float* __restrict__ in, float* __restrict__ out,
                                int K, int N) {
    __shared__ float t[32][33];
    const int n0 = blockIdx.x * 32, k0 = blockIdx.y * 32;
    const int tx = threadIdx.x, ty = threadIdx.y;   // 32 x 8
    #pragma unroll
    for (int j = 0; j < 32; j += 8)
        t[ty + j][tx] = rna_tf32(in[(size_t)(k0 + ty + j) * N + n0 + tx]);
    __syncthreads();
    #pragma unroll
    for (int j = 0; j < 32; j += 8)
        out[(size_t)(n0 + ty + j) * K + k0 + tx] = t[tx][ty + j];
}

// ---------------------------------------------------------------------------
// GRU gate elementwise (folds tiny input projections)
// ---------------------------------------------------------------------------
__global__ void gru_elem(const float* __restrict__ Rh, const float* __restrict__ prev_h,
                         const float* __restrict__ prev_y, const float* __restrict__ ccoarse,
                         const float* __restrict__ Icw, const float* __restrict__ Ifw,
                         const float* __restrict__ bu, const float* __restrict__ br,
                         const float* __restrict__ be,
                         float* __restrict__ hidden) {
    const int idx = blockIdx.x * blockDim.x + threadIdx.x;
    if (idx >= B_SZ * H_SZ) return;
    const int b = idx / H_SZ;
    const int h = idx - b * H_SZ;

    const float py0 = prev_y[2 * b], py1 = prev_y[2 * b + 1];
    float Iu, Ir, Ie;
    if (h < S_SZ) {
        Iu = py0 * Icw[h]            + py1 * Icw[S3 + h];
        Ir = py0 * Icw[S_SZ + h]     + py1 * Icw[S3 + S_SZ + h];
        Ie = py0 * Icw[2 * S_SZ + h] + py1 * Icw[S3 + 2 * S_SZ + h];
    } else {
        const int hh = h - S_SZ;
        const float cc = ccoarse[b];
        Iu = py0 * Ifw[hh]            + py1 * Ifw[S3 + hh]            + cc * Ifw[2 * S3 + hh];
        Ir = py0 * Ifw[S_SZ + hh]     + py1 * Ifw[S3 + S_SZ + hh]     + cc * Ifw[2 * S3 + S_SZ + hh];
        Ie = py0 * Ifw[2 * S_SZ + hh] + py1 * Ifw[S3 + 2 * S_SZ + hh] + cc * Ifw[2 * S3 + 2 * S_SZ + hh];
    }
    const float* r0 = Rh + (size_t)b * H3;
    const float Ru = r0[h], Rr = r0[H_SZ + h], Re = r0[2 * H_SZ + h];

    const float u = 1.0f / (1.0f + expf(-(Ru + Iu + bu[h])));
    const float r = 1.0f / (1.0f + expf(-(Rr + Ir + br[h])));
    const float e = tanhf(r * Re + Ie + be[h]);

    hidden[idx] = u * prev_h[idx] + (1.0f - u) * e;
}

// ---------------------------------------------------------------------------
// Launch
// ---------------------------------------------------------------------------
extern "C" void kernel_launch(void* const* d_in, const int* in_sizes, int n_in,
                              void* d_out, int out_size)
{
    const float* prev_y  = (const float*)d_in[0];
    const float* prev_h  = (const float*)d_in[1];
    const float* ccoarse = (const float*)d_in[2];
    const float* R_W     = (const float*)d_in[3];
    const float* Icw     = (const float*)d_in[4];
    const float* Ifw     = (const float*)d_in[5];
    const float* O1_W    = (const float*)d_in[6];
    const float* O1_b    = (const float*)d_in[7];
    const float* O2_W    = (const float*)d_in[8];
    const float* O2_b    = (const float*)d_in[9];
    const float* O3_W    = (const float*)d_in[10];
    const float* O3_b    = (const float*)d_in[11];
    const float* O4_W    = (const float*)d_in[12];
    const float* O4_b    = (const float*)d_in[13];
    const float* bu      = (const float*)d_in[14];
    const float* br      = (const float*)d_in[15];
    const float* be      = (const float*)d_in[16];

    float* out        = (float*)d_out;
    float* out_coarse = out;
    float* out_fine   = out + (size_t)B_SZ * Q_SZ;
    float* hidden     = out + (size_t)2 * B_SZ * Q_SZ;

    float *Rh, *hc, *hf, *RWt, *O1t, *O2t, *O3t, *O4t;
    cudaGetSymbolAddress((void**)&Rh,  g_Rh);
    cudaGetSymbolAddress((void**)&hc,  g_hc);
    cudaGetSymbolAddress((void**)&hf,  g_hf);
    cudaGetSymbolAddress((void**)&RWt, g_RWt);
    cudaGetSymbolAddress((void**)&O1t, g_O1t);
    cudaGetSymbolAddress((void**)&O2t, g_O2t);
    cudaGetSymbolAddress((void**)&O3t, g_O3t);
    cudaGetSymbolAddress((void**)&O4t, g_O4t);

    const int SMB = 4 * 128 * PITCH * 4;   // 73728 bytes dynamic smem
    cudaFuncSetAttribute(mgemm<0, 1, 0>, cudaFuncAttributeMaxDynamicSharedMemorySize, SMB);
    cudaFuncSetAttribute(mgemm<1, 1, 1>, cudaFuncAttributeMaxDynamicSharedMemorySize, SMB);
    cudaFuncSetAttribute(mgemm<2, 0, 1>, cudaFuncAttributeMaxDynamicSharedMemorySize, SMB);

    // --- weight prep: transpose + RNE tf32 round (tiny) ---
    transpose_round<<<dim3(H3 / 32, H_SZ / 32), dim3(32, 8)>>>(R_W, RWt, H_SZ, H3);
    transpose_round<<<dim3(S_SZ / 32, S_SZ / 32), dim3(32, 8)>>>(O1_W, O1t, S_SZ, S_SZ);
    transpose_round<<<dim3(Q_SZ / 32, S_SZ / 32), dim3(32, 8)>>>(O2_W, O2t, S_SZ, Q_SZ);
    transpose_round<<<dim3(S_SZ / 32, S_SZ / 32), dim3(32, 8)>>>(O3_W, O3t, S_SZ, S_SZ);
    transpose_round<<<dim3(Q_SZ / 32, S_SZ / 32), dim3(32, 8)>>>(O4_W, O4t, S_SZ, Q_SZ);

    const int MT = B_SZ / 128;   // 256 M-tiles

    // 1) Rh = round(prev_h) @ RWt^T
    mgemm<0, 1, 0><<<dim3(H3 / 128, MT, 1), 128, SMB>>>(
        prev_h, nullptr, H_SZ, RWt, nullptr, H_SZ, nullptr, nullptr,
        Rh, nullptr, H3, H3, H_SZ);
    // 2) GRU gates -> hidden (fp32, exact output)
    gru_elem<<<(B_SZ * H_SZ + 255) / 256, 256>>>(Rh, prev_h, prev_y, ccoarse,
                                                 Icw, Ifw, bu, br, be, hidden);
    // 3+4) hc = round(relu(hidden_c @ O1 + b1)); hf = round(relu(hidden_f @ O3 + b3))
    mgemm<1, 1, 1><<<dim3(4, MT, 2), 128, SMB>>>(
        hidden, hidden + S_SZ, H_SZ, O1t, O3t, S_SZ, O1_b, O3_b,
        hc, hf, S_SZ, S_SZ, S_SZ);
    // 5+6) out_coarse = hc @ O2 + b2; out_fine = hf @ O4 + b4
    mgemm<2, 0, 1><<<dim3(2, MT, 2), 128, SMB>>>(
        hc, hf, S_SZ, O2t, O4t, S_SZ, O2_b, O4_b,
        out_coarse, out_fine, Q_SZ, Q_SZ, S_SZ);
}

// round 9
// speedup vs baseline: 5.7000x; 1.7042x over previous
#include <cuda_runtime.h>
#include <cuda_fp16.h>
#include <math.h>
#include <stdint.h>

// Problem dims (fixed)
#define B_SZ 32768
#define H_SZ 896
#define S_SZ 448
#define Q_SZ 256
#define H3   2688
#define S3   1344

// ---------------------------------------------------------------------------
// Scratch (device globals; allocation-free per harness rules)
// ---------------------------------------------------------------------------
__device__ float  g_Rh [(size_t)B_SZ * H3];      // R_hidden fp32
__device__ __half g_Ah [(size_t)B_SZ * H_SZ];    // fp16 prev_hidden
__device__ __half g_hA [(size_t)B_SZ * H_SZ];    // fp16 hidden
__device__ __half g_hc [(size_t)B_SZ * S_SZ];    // fp16 relu head intermediates
__device__ __half g_hf [(size_t)B_SZ * S_SZ];
__device__ __half g_RWt[(size_t)H3 * H_SZ];      // fp16 transposed weights
__device__ __half g_O1t[S_SZ * S_SZ];
__device__ __half g_O2t[Q_SZ * S_SZ];
__device__ __half g_O3t[S_SZ * S_SZ];
__device__ __half g_O4t[Q_SZ * S_SZ];

// ---------------------------------------------------------------------------
// Helpers (non-arch-specific PTX only: must assemble for plain sm_103)
// ---------------------------------------------------------------------------
__device__ __forceinline__ uint32_t smem_u32(const void* p) {
    uint32_t a;
    asm("{ .reg .u64 t; cvta.to.shared.u64 t, %1; cvt.u32.u64 %0, t; }" : "=r"(a) : "l"(p));
    return a;
}
__device__ __forceinline__ void cp_async16(uint32_t s, const void* g) {
    asm volatile("cp.async.cg.shared.global [%0], [%1], 16;\n" :: "r"(s), "l"(g));
}
__device__ __forceinline__ void cp_async16_pred(uint32_t s, const void* g, int sz) {
    asm volatile("cp.async.cg.shared.global [%0], [%1], 16, %2;\n"
                 :: "r"(s), "l"(g), "r"(sz));
}
#define CP_COMMIT()  asm volatile("cp.async.commit_group;\n" ::)
#define CP_WAIT(n)   asm volatile("cp.async.wait_group %0;\n" :: "n"(n))

__device__ __forceinline__ void mma_16816(float* d, const uint32_t* a, const uint32_t* b) {
    asm volatile(
        "mma.sync.aligned.m16n8k16.row.col.f32.f16.f16.f32 "
        "{%0,%1,%2,%3}, {%4,%5,%6,%7}, {%8,%9}, {%0,%1,%2,%3};"
        : "+f"(d[0]), "+f"(d[1]), "+f"(d[2]), "+f"(d[3])
        : "r"(a[0]), "r"(a[1]), "r"(a[2]), "r"(a[3]), "r"(b[0]), "r"(b[1]));
}

// ---------------------------------------------------------------------------
// fp16 mma.sync GEMM: C[M,N] = A[M,K] @ Bt[N,K]^T (+bias)(+relu)
// CTA 128x128, BK=64 (fp16), 128 thr = 4 warps (2x2), warp tile 64x64.
// A,Bt fp16 in gmem. Accumulate fp32.
// EPI: 0=none, 1=bias+relu, 2=bias.  HOUT: 1 = write __half C, 0 = float C.
// DUAL: blockIdx.z selects problem set.
// ---------------------------------------------------------------------------
#define PW   36                   // words (4B) per smem row: 64 halves + 8 pad
#define MATW (128 * PW)           // words per matrix per buffer

template <int EPI, int HOUT, int DUAL>
__global__ void __launch_bounds__(128, 2)
hgemm(const __half* __restrict__ A0, const __half* __restrict__ A1, int lda,
      const __half* __restrict__ B0, const __half* __restrict__ B1, int ldb,
      const float* __restrict__ bias0, const float* __restrict__ bias1,
      void* __restrict__ C0v, void* __restrict__ C1v, int ldc, int N, int K)
{
    extern __shared__ uint32_t smw[];   // [2 buf][A|B][128][PW]
    const __half* A    = (DUAL && blockIdx.z) ? A1 : A0;
    const __half* Bt   = (DUAL && blockIdx.z) ? B1 : B0;
    const float*  bias = (DUAL && blockIdx.z) ? bias1 : bias0;
    void*         Cv   = (DUAL && blockIdx.z) ? C1v : C0v;

    const int tid = threadIdx.x;
    const int lane = tid & 31, w = tid >> 5;
    const int wr = w >> 1, wc = w & 1;        // 2x2 warps, warp tile 64x64
    const int lq = lane >> 2, ln = lane & 3;

    const int rowBase = blockIdx.y * 128;
    const int colBase = blockIdx.x * 128;

    const uint32_t sBase = smem_u32(smw);

    // cp.async: per matrix per iter 128 rows x 128B = 1024 chunks; 8/thread.
    const int r0 = tid >> 3, c16 = tid & 7;           // row 0..15, 16B-col 0..7
    const uint32_t dstOff = (uint32_t)((r0 * PW + c16 * 4) * 4);   // bytes
    const __half* Abase = A + (size_t)(rowBase + r0) * lda + c16 * 8;

    auto load_tile = [&](int buf, int it) {
        const int kb = it * 64;
        const uint32_t base = sBase + (uint32_t)(buf * 2 * MATW * 4);
        #pragma unroll
        for (int i = 0; i < 8; ++i)
            cp_async16(base + dstOff + (uint32_t)(i * 16 * PW * 4),
                       Abase + kb + (size_t)(i * 16) * lda);
        #pragma unroll
        for (int i = 0; i < 8; ++i) {
            const int bn = colBase + r0 + 16 * i;
            const int sz = (bn < N) ? 16 : 0;
            const __half* gp = Bt + (size_t)(sz ? bn : 0) * ldb + c16 * 8 + kb;
            cp_async16_pred(base + (uint32_t)(MATW * 4) + dstOff + (uint32_t)(i * 16 * PW * 4),
                            gp, sz);
        }
        CP_COMMIT();
    };

    float acc[4][8][4];
    #pragma unroll
    for (int i = 0; i < 4; ++i)
        #pragma unroll
        for (int j = 0; j < 8; ++j)
            #pragma unroll
            for (int k = 0; k < 4; ++k) acc[i][j][k] = 0.0f;

    const int nit = K >> 6;
    load_tile(0, 0);

    for (int it = 0; it < nit; ++it) {
        const int buf = it & 1;
        if (it + 1 < nit) { load_tile(buf ^ 1, it + 1); CP_WAIT(1); }
        else              { CP_WAIT(0); }
        __syncthreads();

        const uint32_t* Ab = smw + buf * 2 * MATW;
        const uint32_t* Bb = Ab + MATW;

        #pragma unroll
        for (int s = 0; s < 4; ++s) {          // 4 x K=16 steps
            const int k8 = s * 8;              // word offset within row
            uint32_t a[4][4], b[8][2];
            #pragma unroll
            for (int mf = 0; mf < 4; ++mf) {
                const int m = wr * 64 + mf * 16 + lq;
                a[mf][0] = Ab[m * PW + k8 + ln];
                a[mf][1] = Ab[(m + 8) * PW + k8 + ln];
                a[mf][2] = Ab[m * PW + k8 + ln + 4];
                a[mf][3] = Ab[(m + 8) * PW + k8 + ln + 4];
            }
            #pragma unroll
            for (int nf = 0; nf < 8; ++nf) {
                const int n = wc * 64 + nf * 8 + lq;
                b[nf][0] = Bb[n * PW + k8 + ln];
                b[nf][1] = Bb[n * PW + k8 + ln + 4];
            }
            #pragma unroll
            for (int mf = 0; mf < 4; ++mf)
                #pragma unroll
                for (int nf = 0; nf < 8; ++nf)
                    mma_16816(acc[mf][nf], a[mf], b[nf]);
        }
        __syncthreads();
    }

    // ---- epilogue ----
    #pragma unroll
    for (int nf = 0; nf < 8; ++nf) {
        const int col = colBase + wc * 64 + nf * 8 + ln * 2;
        if (col < N) {
            float2 bv = make_float2(0.0f, 0.0f);
            if (EPI) bv = *reinterpret_cast<const float2*>(bias + col);
            #pragma unroll
            for (int mf = 0; mf < 4; ++mf) {
                const int row = rowBase + wr * 64 + mf * 16 + lq;
                float2 v0 = make_float2(acc[mf][nf][0], acc[mf][nf][1]);
                float2 v1 = make_float2(acc[mf][nf][2], acc[mf][nf][3]);
                if (EPI) {
                    v0.x += bv.x; v0.y += bv.y; v1.x += bv.x; v1.y += bv.y;
                    if (EPI == 1) {
                        v0.x = fmaxf(v0.x, 0.0f); v0.y = fmaxf(v0.y, 0.0f);
                        v1.x = fmaxf(v1.x, 0.0f); v1.y = fmaxf(v1.y, 0.0f);
                    }
                }
                if (HOUT) {
                    __half* Ch = (__half*)Cv;
                    *reinterpret_cast<__half2*>(Ch + (size_t)row * ldc + col) =
                        __floats2half2_rn(v0.x, v0.y);
                    *reinterpret_cast<__half2*>(Ch + (size_t)(row + 8) * ldc + col) =
                        __floats2half2_rn(v1.x, v1.y);
                } else {
                    float* Cf = (float*)Cv;
                    *reinterpret_cast<float2*>(Cf + (size_t)row * ldc + col) = v0;
                    *reinterpret_cast<float2*>(Cf + (size_t)(row + 8) * ldc + col) = v1;
                }
            }
        }
    }
}

// ---------------------------------------------------------------------------
// Prep: fp32 -> fp16 bulk convert
// ---------------------------------------------------------------------------
__global__ void f2h(const float4* __restrict__ in, __half2* __restrict__ out, int n4) {
    const int i = blockIdx.x * blockDim.x + threadIdx.x;
    if (i < n4) {
        float4 v = in[i];
        out[2 * i]     = __floats2half2_rn(v.x, v.y);
        out[2 * i + 1] = __floats2half2_rn(v.z, v.w);
    }
}

// Weight prep: [K,N] fp32 row-major -> [N,K] fp16 row-major (dual via blockIdx.z)
__global__ void transpose_h(const float* __restrict__ in0, const float* __restrict__ in1,
                            __half* __restrict__ out0, __half* __restrict__ out1,
                            int K, int N) {
    __shared__ float t[32][33];
    const float* in  = blockIdx.z ? in1 : in0;
    __half*      out = blockIdx.z ? out1 : out0;
    const int n0 = blockIdx.x * 32, k0 = blockIdx.y * 32;
    const int tx = threadIdx.x, ty = threadIdx.y;   // 32 x 8
    #pragma unroll
    for (int j = 0; j < 32; j += 8)
        t[ty + j][tx] = in[(size_t)(k0 + ty + j) * N + n0 + tx];
    __syncthreads();
    #pragma unroll
    for (int j = 0; j < 32; j += 8)
        out[(size_t)(n0 + ty + j) * K + k0 + tx] = __float2half_rn(t[tx][ty + j]);
}

// ---------------------------------------------------------------------------
// GRU gate elementwise; emits fp32 hidden (output) + fp16 copy for head GEMMs
// ---------------------------------------------------------------------------
__global__ void gru_elem(const float* __restrict__ Rh, const float* __restrict__ prev_h,
                         const float* __restrict__ prev_y, const float* __restrict__ ccoarse,
                         const float* __restrict__ Icw, const float* __restrict__ Ifw,
                         const float* __restrict__ bu, const float* __restrict__ br,
                         const float* __restrict__ be,
                         float* __restrict__ hidden, __half* __restrict__ hA) {
    const int idx = blockIdx.x * blockDim.x + threadIdx.x;
    if (idx >= B_SZ * H_SZ) return;
    const int b = idx / H_SZ;
    const int h = idx - b * H_SZ;

    const float py0 = prev_y[2 * b], py1 = prev_y[2 * b + 1];
    float Iu, Ir, Ie;
    if (h < S_SZ) {
        Iu = py0 * Icw[h]            + py1 * Icw[S3 + h];
        Ir = py0 * Icw[S_SZ + h]     + py1 * Icw[S3 + S_SZ + h];
        Ie = py0 * Icw[2 * S_SZ + h] + py1 * Icw[S3 + 2 * S_SZ + h];
    } else {
        const int hh = h - S_SZ;
        const float cc = ccoarse[b];
        Iu = py0 * Ifw[hh]            + py1 * Ifw[S3 + hh]            + cc * Ifw[2 * S3 + hh];
        Ir = py0 * Ifw[S_SZ + hh]     + py1 * Ifw[S3 + S_SZ + hh]     + cc * Ifw[2 * S3 + S_SZ + hh];
        Ie = py0 * Ifw[2 * S_SZ + hh] + py1 * Ifw[S3 + 2 * S_SZ + hh] + cc * Ifw[2 * S3 + 2 * S_SZ + hh];
    }
    const float* r0 = Rh + (size_t)b * H3;
    const float Ru = r0[h], Rr = r0[H_SZ + h], Re = r0[2 * H_SZ + h];

    const float u = 1.0f / (1.0f + expf(-(Ru + Iu + bu[h])));
    const float r = 1.0f / (1.0f + expf(-(Rr + Ir + br[h])));
    const float e = tanhf(r * Re + Ie + be[h]);

    const float hv = u * prev_h[idx] + (1.0f - u) * e;
    hidden[idx] = hv;
    hA[idx] = __float2half_rn(hv);
}

// ---------------------------------------------------------------------------
// Launch
// ---------------------------------------------------------------------------
extern "C" void kernel_launch(void* const* d_in, const int* in_sizes, int n_in,
                              void* d_out, int out_size)
{
    const float* prev_y  = (const float*)d_in[0];
    const float* prev_h  = (const float*)d_in[1];
    const float* ccoarse = (const float*)d_in[2];
    const float* R_W     = (const float*)d_in[3];
    const float* Icw     = (const float*)d_in[4];
    const float* Ifw     = (const float*)d_in[5];
    const float* O1_W    = (const float*)d_in[6];
    const float* O1_b    = (const float*)d_in[7];
    const float* O2_W    = (const float*)d_in[8];
    const float* O2_b    = (const float*)d_in[9];
    const float* O3_W    = (const float*)d_in[10];
    const float* O3_b    = (const float*)d_in[11];
    const float* O4_W    = (const float*)d_in[12];
    const float* O4_b    = (const float*)d_in[13];
    const float* bu      = (const float*)d_in[14];
    const float* br      = (const float*)d_in[15];
    const float* be      = (const float*)d_in[16];

    float* out        = (float*)d_out;
    float* out_coarse = out;
    float* out_fine   = out + (size_t)B_SZ * Q_SZ;
    float* hidden     = out + (size_t)2 * B_SZ * Q_SZ;

    float* Rh;
    __half *Ah, *hA, *hc, *hf, *RWt, *O1t, *O2t, *O3t, *O4t;
    cudaGetSymbolAddress((void**)&Rh,  g_Rh);
    cudaGetSymbolAddress((void**)&Ah,  g_Ah);
    cudaGetSymbolAddress((void**)&hA,  g_hA);
    cudaGetSymbolAddress((void**)&hc,  g_hc);
    cudaGetSymbolAddress((void**)&hf,  g_hf);
    cudaGetSymbolAddress((void**)&RWt, g_RWt);
    cudaGetSymbolAddress((void**)&O1t, g_O1t);
    cudaGetSymbolAddress((void**)&O2t, g_O2t);
    cudaGetSymbolAddress((void**)&O3t, g_O3t);
    cudaGetSymbolAddress((void**)&O4t, g_O4t);

    const int SMB = 4 * MATW * 4;   // 73728 bytes dynamic smem
    cudaFuncSetAttribute(hgemm<0, 0, 0>, cudaFuncAttributeMaxDynamicSharedMemorySize, SMB);
    cudaFuncSetAttribute(hgemm<1, 1, 1>, cudaFuncAttributeMaxDynamicSharedMemorySize, SMB);
    cudaFuncSetAttribute(hgemm<2, 0, 1>, cudaFuncAttributeMaxDynamicSharedMemorySize, SMB);

    // --- prep (exactly 5 launches so ncu -s 5 captures the big GEMM) ---
    const int n4 = B_SZ * H_SZ / 4;
    f2h<<<(n4 + 255) / 256, 256>>>((const float4*)prev_h, (__half2*)Ah, n4);
    transpose_h<<<dim3(H3 / 32, H_SZ / 32, 1), dim3(32, 8)>>>(R_W, R_W, RWt, RWt, H_SZ, H3);
    transpose_h<<<dim3(S_SZ / 32, S_SZ / 32, 2), dim3(32, 8)>>>(O1_W, O3_W, O1t, O3t, S_SZ, S_SZ);
    transpose_h<<<dim3(Q_SZ / 32, S_SZ / 32, 1), dim3(32, 8)>>>(O2_W, O2_W, O2t, O2t, S_SZ, Q_SZ);
    transpose_h<<<dim3(Q_SZ / 32, S_SZ / 32, 1), dim3(32, 8)>>>(O4_W, O4_W, O4t, O4t, S_SZ, Q_SZ);

    const int MT = B_SZ / 128;   // 256 M-tiles

    // 1) Rh = Ah @ RWt^T   (fp16 in, fp32 out)
    hgemm<0, 0, 0><<<dim3(H3 / 128, MT, 1), 128, SMB>>>(
        Ah, nullptr, H_SZ, RWt, nullptr, H_SZ, nullptr, nullptr,
        Rh, nullptr, H3, H3, H_SZ);
    // 2) GRU gates -> hidden (fp32) + fp16 copy
    gru_elem<<<(B_SZ * H_SZ + 255) / 256, 256>>>(Rh, prev_h, prev_y, ccoarse,
                                                 Icw, Ifw, bu, br, be, hidden, hA);
    // 3+4) hc = relu(hidden_c @ O1 + b1) [fp16]; hf = relu(hidden_f @ O3 + b3) [fp16]
    hgemm<1, 1, 1><<<dim3(4, MT, 2), 128, SMB>>>(
        hA, hA + S_SZ, H_SZ, O1t, O3t, S_SZ, O1_b, O3_b,
        hc, hf, S_SZ, S_SZ, S_SZ);
    // 5+6) out_coarse = hc @ O2 + b2; out_fine = hf @ O4 + b4 (fp32 out)
    hgemm<2, 0, 1><<<dim3(2, MT, 2), 128, SMB>>>(
        hc, hf, S_SZ, O2t, O4t, S_SZ, O2_b, O4_b,
        out_coarse, out_fine, Q_SZ, Q_SZ, S_SZ);
}